// round 12
// baseline (speedup 1.0000x reference)
#include <cuda_runtime.h>

// YOLOv1 loss: pred [N,30,7,7] f32, labels [N,30,7,7] f32 -> scalar f32.
// HBM-bound streaming reduction at the measured floor (~6.9 TB/s on ~720 MB).
// Finalize-free: a tiny PRIMARY kernel zeroes out[0]; the main kernel is
// PDL-launched (overlaps the zero kernel), and each block griddepcontrol.wait's
// only right before its single atomicAdd of the pre-scaled float partial into
// out[0]. Nothing runs after the main grid -> no exposed tail.

#define OBJ_W   5.0f
#define NOOBJ_W 0.1f
#define EPS_F   1e-10f

#define BLOCK 256

__device__ __forceinline__ float iou_f(float acx, float acy, float aw, float ah,
                                       float bcx, float bcy, float bw, float bh) {
    float ax1 = acx - aw * 0.5f, ax2 = acx + aw * 0.5f;
    float ay1 = acy - ah * 0.5f, ay2 = acy + ah * 0.5f;
    float bx1 = bcx - bw * 0.5f, bx2 = bcx + bw * 0.5f;
    float by1 = bcy - bh * 0.5f, by2 = bcy + bh * 0.5f;
    float iw = fminf(ax2, bx2) - fmaxf(ax1, bx1);
    float ih = fminf(ay2, by2) - fmaxf(ay1, by1);
    iw = fmaxf(iw, 0.0f);
    ih = fmaxf(ih, 0.0f);
    float inter  = iw * ih;
    float area_a = (ax2 - ax1) * (ay2 - ay1);
    float area_b = (bx2 - bx1) * (by2 - by1);
    return inter / (area_a + area_b - inter + EPS_F);
}

__global__ void yolo_zero_kernel(float* __restrict__ out) {
    out[0] = 0.0f;
    // Let the dependent (main) grid launch immediately.
    asm volatile("griddepcontrol.launch_dependents;");
}

__global__ __launch_bounds__(BLOCK)
void yolo_loss_kernel(const float* __restrict__ pred,
                      const float* __restrict__ labels,
                      float* __restrict__ out,
                      int total_cells, float inv_N) {
    int m = blockIdx.x * BLOCK + threadIdx.x;
    float loss = 0.0f;

    if (m < total_cells) {
        int n = m / 49;              // image index
        int s = m - n * 49;          // spatial cell (i*7+j)
        long long base = (long long)n * 1470 + s;   // 30*49 = 1470
        const float* __restrict__ P = pred + base;
        const float* __restrict__ L = labels + base;

        // pred channels 0..9
        float p[10];
        #pragma unroll
        for (int c = 0; c < 10; c++) p[c] = P[c * 49];

        // label channels needed individually
        float l0 = L[0 * 49], l1 = L[1 * 49], l2 = L[2 * 49], l3 = L[3 * 49];
        float l4 = L[4 * 49], l9 = L[9 * 49];

        // classification sum (channels 10..29), fully unrolled (max MLP)
        float cls = 0.0f;
        #pragma unroll
        for (int c = 10; c < 30; c++) {
            float d = P[c * 49] - L[c * 49];
            cls = fmaf(d, d, cls);
        }

        float objf   = (l4 == 1.0f) ? 1.0f : 0.0f;
        float noobjf = 1.0f - objf;

        float iou1 = iou_f(p[0], p[1], p[2], p[3], l0, l1, l2, l3);
        float iou2 = iou_f(p[5], p[6], p[7], p[8], l0, l1, l2, l3);
        bool sel1 = (iou1 >= iou2);

        // confidence term
        float dc1 = p[4] - l4;
        float dc2 = p[9] - l9;
        float conf = sel1 ? dc1 * dc1 : dc2 * dc2;

        // noobj terms
        float dn1 = p[9] - iou1;
        float dn2 = p[4] - iou2;
        float noobj_in  = sel1 ? dn1 * dn1 : dn2 * dn2;
        float noobj_out = p[4] * p[4] + p[9] * p[9];

        // bbox term for selected box
        float bcx = sel1 ? p[0] : p[5];
        float bcy = sel1 ? p[1] : p[6];
        float bw  = sel1 ? p[2] : p[7];
        float bh  = sel1 ? p[3] : p[8];
        float dx = bcx - l0, dy = bcy - l1;
        float dw = sqrtf(bw) - sqrtf(l2);
        float dh = sqrtf(bh) - sqrtf(l3);
        float bbox = dx * dx + dy * dy + dw * dw + dh * dh;

        loss = objf * conf
             + NOOBJ_W * (objf * noobj_in + noobjf * noobj_out)
             + OBJ_W * objf * bbox
             + objf * cls;
    }

    // warp reduce
    #pragma unroll
    for (int o = 16; o > 0; o >>= 1)
        loss += __shfl_down_sync(0xffffffffu, loss, o);

    __shared__ float ws[BLOCK / 32];
    int lane = threadIdx.x & 31;
    int wid  = threadIdx.x >> 5;
    if (lane == 0) ws[wid] = loss;
    __syncthreads();

    if (wid == 0 && lane == 0) {
        float v = ws[0];
        #pragma unroll
        for (int w = 1; w < BLOCK / 32; w++) v += ws[w];
        // Ensure the primary (zero) grid's write to out[0] is visible,
        // then accumulate this block's pre-scaled partial directly.
        asm volatile("griddepcontrol.wait;");
        atomicAdd(out, v * inv_N);
    }
}

extern "C" void kernel_launch(void* const* d_in, const int* in_sizes, int n_in,
                              void* d_out, int out_size) {
    const float* pred   = (const float*)d_in[0];
    const float* labels = (const float*)d_in[1];
    float* out = (float*)d_out;

    int N = in_sizes[0] / (30 * 49);
    int total_cells = N * 49;
    int blocks = (total_cells + BLOCK - 1) / BLOCK;
    float inv_N = 1.0f / (float)N;

    // Primary: zero the output scalar (and release dependents immediately).
    yolo_zero_kernel<<<1, 1>>>(out);

    // Secondary: main streaming kernel, PDL-launched to overlap the primary.
    cudaLaunchConfig_t cfg = {};
    cfg.gridDim  = dim3((unsigned)blocks, 1, 1);
    cfg.blockDim = dim3(BLOCK, 1, 1);
    cfg.dynamicSmemBytes = 0;
    cfg.stream = 0;
    cudaLaunchAttribute attrs[1];
    attrs[0].id = cudaLaunchAttributeProgrammaticStreamSerialization;
    attrs[0].val.programmaticStreamSerializationAllowed = 1;
    cfg.attrs = attrs;
    cfg.numAttrs = 1;
    cudaLaunchKernelEx(&cfg, yolo_loss_kernel, pred, labels, out, total_cells, inv_N);
}

// round 14
// speedup vs baseline: 1.0053x; 1.0053x over previous
#include <cuda_runtime.h>

// YOLOv1 loss: pred [N,30,7,7] f32, labels [N,30,7,7] f32 -> scalar f32.
// CONVERGED CONFIG (R6): HBM-bound streaming reduction at the measured floor
// (~6.9 TB/s on ~725 MB actual traffic, ~88% of spec).
//  - 256-thread blocks, natural ~40 regs (max MLP_eff; reg caps and other
//    block sizes measured slower), fully-unrolled loads.
//  - One f64 atomicAdd per block into g_acc.
//  - PDL-overlapped finalize kernel: griddepcontrol hides its launch; it
//    reads g_acc, writes out[0], and resets g_acc for graph replay.

#define OBJ_W   5.0f
#define NOOBJ_W 0.1f
#define EPS_F   1e-10f

__device__ double g_acc = 0.0;

__device__ __forceinline__ float iou_f(float acx, float acy, float aw, float ah,
                                       float bcx, float bcy, float bw, float bh) {
    float ax1 = acx - aw * 0.5f, ax2 = acx + aw * 0.5f;
    float ay1 = acy - ah * 0.5f, ay2 = acy + ah * 0.5f;
    float bx1 = bcx - bw * 0.5f, bx2 = bcx + bw * 0.5f;
    float by1 = bcy - bh * 0.5f, by2 = bcy + bh * 0.5f;
    float iw = fminf(ax2, bx2) - fmaxf(ax1, bx1);
    float ih = fminf(ay2, by2) - fmaxf(ay1, by1);
    iw = fmaxf(iw, 0.0f);
    ih = fmaxf(ih, 0.0f);
    float inter  = iw * ih;
    float area_a = (ax2 - ax1) * (ay2 - ay1);
    float area_b = (bx2 - bx1) * (by2 - by1);
    return inter / (area_a + area_b - inter + EPS_F);
}

__global__ __launch_bounds__(256)
void yolo_loss_kernel(const float* __restrict__ pred,
                      const float* __restrict__ labels,
                      int total_cells) {
    int m = blockIdx.x * 256 + threadIdx.x;
    float loss = 0.0f;

    if (m < total_cells) {
        int n = m / 49;              // image index
        int s = m - n * 49;          // spatial cell (i*7+j)
        long long base = (long long)n * 1470 + s;   // 30*49 = 1470
        const float* __restrict__ P = pred + base;
        const float* __restrict__ L = labels + base;

        // pred channels 0..9
        float p[10];
        #pragma unroll
        for (int c = 0; c < 10; c++) p[c] = P[c * 49];

        // label channels needed individually
        float l0 = L[0 * 49], l1 = L[1 * 49], l2 = L[2 * 49], l3 = L[3 * 49];
        float l4 = L[4 * 49], l9 = L[9 * 49];

        // classification sum (channels 10..29), fully unrolled (max MLP)
        float cls = 0.0f;
        #pragma unroll
        for (int c = 10; c < 30; c++) {
            float d = P[c * 49] - L[c * 49];
            cls = fmaf(d, d, cls);
        }

        float objf   = (l4 == 1.0f) ? 1.0f : 0.0f;
        float noobjf = 1.0f - objf;

        float iou1 = iou_f(p[0], p[1], p[2], p[3], l0, l1, l2, l3);
        float iou2 = iou_f(p[5], p[6], p[7], p[8], l0, l1, l2, l3);
        bool sel1 = (iou1 >= iou2);

        // confidence term
        float dc1 = p[4] - l4;
        float dc2 = p[9] - l9;
        float conf = sel1 ? dc1 * dc1 : dc2 * dc2;

        // noobj terms
        float dn1 = p[9] - iou1;
        float dn2 = p[4] - iou2;
        float noobj_in  = sel1 ? dn1 * dn1 : dn2 * dn2;
        float noobj_out = p[4] * p[4] + p[9] * p[9];

        // bbox term for selected box
        float bcx = sel1 ? p[0] : p[5];
        float bcy = sel1 ? p[1] : p[6];
        float bw  = sel1 ? p[2] : p[7];
        float bh  = sel1 ? p[3] : p[8];
        float dx = bcx - l0, dy = bcy - l1;
        float dw = sqrtf(bw) - sqrtf(l2);
        float dh = sqrtf(bh) - sqrtf(l3);
        float bbox = dx * dx + dy * dy + dw * dw + dh * dh;

        loss = objf * conf
             + NOOBJ_W * (objf * noobj_in + noobjf * noobj_out)
             + OBJ_W * objf * bbox
             + objf * cls;
    }

    // warp reduce
    #pragma unroll
    for (int o = 16; o > 0; o >>= 1)
        loss += __shfl_down_sync(0xffffffffu, loss, o);

    __shared__ float ws[8];
    int lane = threadIdx.x & 31;
    int wid  = threadIdx.x >> 5;
    if (lane == 0) ws[wid] = loss;
    __syncthreads();

    if (wid == 0 && lane == 0) {
        float v = ws[0];
        #pragma unroll
        for (int w = 1; w < 8; w++) v += ws[w];
        atomicAdd(&g_acc, (double)v);
    }

    // Allow the dependent (finalize) grid to launch once all CTAs signal.
    asm volatile("griddepcontrol.launch_dependents;");
}

__global__ void yolo_finalize_kernel(float* __restrict__ out, int N) {
    // Wait until the primary grid's memory operations are visible.
    asm volatile("griddepcontrol.wait;");
    out[0] = (float)(g_acc / (double)N);
    g_acc = 0.0;   // reset for next graph replay (kernel boundary orders this)
}

extern "C" void kernel_launch(void* const* d_in, const int* in_sizes, int n_in,
                              void* d_out, int out_size) {
    const float* pred   = (const float*)d_in[0];
    const float* labels = (const float*)d_in[1];
    float* out = (float*)d_out;

    int N = in_sizes[0] / (30 * 49);
    int total_cells = N * 49;
    int blocks = (total_cells + 255) / 256;

    yolo_loss_kernel<<<blocks, 256>>>(pred, labels, total_cells);

    cudaLaunchConfig_t cfg = {};
    cfg.gridDim  = dim3(1, 1, 1);
    cfg.blockDim = dim3(1, 1, 1);
    cfg.dynamicSmemBytes = 0;
    cfg.stream = 0;
    cudaLaunchAttribute attrs[1];
    attrs[0].id = cudaLaunchAttributeProgrammaticStreamSerialization;
    attrs[0].val.programmaticStreamSerializationAllowed = 1;
    cfg.attrs = attrs;
    cfg.numAttrs = 1;
    cudaLaunchKernelEx(&cfg, yolo_finalize_kernel, out, N);
}

// round 16
// speedup vs baseline: 1.0296x; 1.0242x over previous
#include <cuda_runtime.h>

// YOLOv1 loss: pred [N,30,7,7] f32, labels [N,30,7,7] f32 -> scalar f32.
// Converged R6 config (256-thr blocks, natural ~40 regs, fully-unrolled
// loads, one f64 atomic per block, PDL-overlapped finalize) + L2::256B
// prefetch-hinted streaming loads to nudge DRAM utilization.

#define OBJ_W   5.0f
#define NOOBJ_W 0.1f
#define EPS_F   1e-10f

__device__ double g_acc = 0.0;

// Streaming load with L2 256B prefetch hint. Non-volatile asm: ptxas keeps
// full freedom to batch/hoist these (preserves the front-batched MLP).
__device__ __forceinline__ float ldg_pf(const float* p) {
    float v;
    asm("ld.global.nc.L2::256B.f32 %0, [%1];" : "=f"(v) : "l"(p));
    return v;
}

__device__ __forceinline__ float iou_f(float acx, float acy, float aw, float ah,
                                       float bcx, float bcy, float bw, float bh) {
    float ax1 = acx - aw * 0.5f, ax2 = acx + aw * 0.5f;
    float ay1 = acy - ah * 0.5f, ay2 = acy + ah * 0.5f;
    float bx1 = bcx - bw * 0.5f, bx2 = bcx + bw * 0.5f;
    float by1 = bcy - bh * 0.5f, by2 = bcy + bh * 0.5f;
    float iw = fminf(ax2, bx2) - fmaxf(ax1, bx1);
    float ih = fminf(ay2, by2) - fmaxf(ay1, by1);
    iw = fmaxf(iw, 0.0f);
    ih = fmaxf(ih, 0.0f);
    float inter  = iw * ih;
    float area_a = (ax2 - ax1) * (ay2 - ay1);
    float area_b = (bx2 - bx1) * (by2 - by1);
    return inter / (area_a + area_b - inter + EPS_F);
}

__global__ __launch_bounds__(256)
void yolo_loss_kernel(const float* __restrict__ pred,
                      const float* __restrict__ labels,
                      int total_cells) {
    int m = blockIdx.x * 256 + threadIdx.x;
    float loss = 0.0f;

    if (m < total_cells) {
        int n = m / 49;              // image index
        int s = m - n * 49;          // spatial cell (i*7+j)
        long long base = (long long)n * 1470 + s;   // 30*49 = 1470
        const float* __restrict__ P = pred + base;
        const float* __restrict__ L = labels + base;

        // pred channels 0..9
        float p[10];
        #pragma unroll
        for (int c = 0; c < 10; c++) p[c] = ldg_pf(P + c * 49);

        // label channels needed individually
        float l0 = ldg_pf(L + 0 * 49), l1 = ldg_pf(L + 1 * 49);
        float l2 = ldg_pf(L + 2 * 49), l3 = ldg_pf(L + 3 * 49);
        float l4 = ldg_pf(L + 4 * 49), l9 = ldg_pf(L + 9 * 49);

        // classification sum (channels 10..29), fully unrolled (max MLP)
        float cls = 0.0f;
        #pragma unroll
        for (int c = 10; c < 30; c++) {
            float d = ldg_pf(P + c * 49) - ldg_pf(L + c * 49);
            cls = fmaf(d, d, cls);
        }

        float objf   = (l4 == 1.0f) ? 1.0f : 0.0f;
        float noobjf = 1.0f - objf;

        float iou1 = iou_f(p[0], p[1], p[2], p[3], l0, l1, l2, l3);
        float iou2 = iou_f(p[5], p[6], p[7], p[8], l0, l1, l2, l3);
        bool sel1 = (iou1 >= iou2);

        // confidence term
        float dc1 = p[4] - l4;
        float dc2 = p[9] - l9;
        float conf = sel1 ? dc1 * dc1 : dc2 * dc2;

        // noobj terms
        float dn1 = p[9] - iou1;
        float dn2 = p[4] - iou2;
        float noobj_in  = sel1 ? dn1 * dn1 : dn2 * dn2;
        float noobj_out = p[4] * p[4] + p[9] * p[9];

        // bbox term for selected box
        float bcx = sel1 ? p[0] : p[5];
        float bcy = sel1 ? p[1] : p[6];
        float bw  = sel1 ? p[2] : p[7];
        float bh  = sel1 ? p[3] : p[8];
        float dx = bcx - l0, dy = bcy - l1;
        float dw = sqrtf(bw) - sqrtf(l2);
        float dh = sqrtf(bh) - sqrtf(l3);
        float bbox = dx * dx + dy * dy + dw * dw + dh * dh;

        loss = objf * conf
             + NOOBJ_W * (objf * noobj_in + noobjf * noobj_out)
             + OBJ_W * objf * bbox
             + objf * cls;
    }

    // warp reduce
    #pragma unroll
    for (int o = 16; o > 0; o >>= 1)
        loss += __shfl_down_sync(0xffffffffu, loss, o);

    __shared__ float ws[8];
    int lane = threadIdx.x & 31;
    int wid  = threadIdx.x >> 5;
    if (lane == 0) ws[wid] = loss;
    __syncthreads();

    if (wid == 0 && lane == 0) {
        float v = ws[0];
        #pragma unroll
        for (int w = 1; w < 8; w++) v += ws[w];
        atomicAdd(&g_acc, (double)v);
    }

    // Allow the dependent (finalize) grid to launch once all CTAs signal.
    asm volatile("griddepcontrol.launch_dependents;");
}

__global__ void yolo_finalize_kernel(float* __restrict__ out, int N) {
    // Wait until the primary grid's memory operations are visible.
    asm volatile("griddepcontrol.wait;");
    out[0] = (float)(g_acc / (double)N);
    g_acc = 0.0;   // reset for next graph replay (kernel boundary orders this)
}

extern "C" void kernel_launch(void* const* d_in, const int* in_sizes, int n_in,
                              void* d_out, int out_size) {
    const float* pred   = (const float*)d_in[0];
    const float* labels = (const float*)d_in[1];
    float* out = (float*)d_out;

    int N = in_sizes[0] / (30 * 49);
    int total_cells = N * 49;
    int blocks = (total_cells + 255) / 256;

    yolo_loss_kernel<<<blocks, 256>>>(pred, labels, total_cells);

    cudaLaunchConfig_t cfg = {};
    cfg.gridDim  = dim3(1, 1, 1);
    cfg.blockDim = dim3(1, 1, 1);
    cfg.dynamicSmemBytes = 0;
    cfg.stream = 0;
    cudaLaunchAttribute attrs[1];
    attrs[0].id = cudaLaunchAttributeProgrammaticStreamSerialization;
    attrs[0].val.programmaticStreamSerializationAllowed = 1;
    cfg.attrs = attrs;
    cfg.numAttrs = 1;
    cudaLaunchKernelEx(&cfg, yolo_finalize_kernel, out, N);
}